// round 15
// baseline (speedup 1.0000x reference)
#include <cuda_runtime.h>
#include <cuda_fp16.h>
#include <math.h>
#include <stdint.h>

typedef unsigned long long u64;

#define NPTS 65536
#define KC   4096
#define DD   64
#define BM   128
#define BN   128
#define NTHREADS 256
#define THETA_FLAG 3.5e-5f
#define THETA_CAND 3.2e-5f
#define YOFF 0.03125f
#define CCAP 16

/* k_hmma/k_cand smem offsets (from 128B-aligned base) */
#define SA   0          /* A tile: 128 rows x 128B (swizzled); reused as merge space */
#define SB0  16384
#define SB1  32768
#define SE0  49152      /* e2o chunk: 128 floats */
#define SE1  49664
#define SMEM_H (50176 + 128)

/* ---------------- device scratch ---------------- */
__device__ float g_e2[KC];
__device__ float g_e2o[KC];
__device__ int   g_counts[KC];
__device__ float g_sqsum;
__device__ int   g_idx[NPTS];
__device__ int   g_flag_cnt;
__device__ int   g_flag_list[NPTS];
__device__ float g_b1f[NPTS];
__device__ int   g_ccnt[NPTS];
__device__ int   g_cand[(size_t)NPTS * CCAP];             /* 4 MB */
__device__ __align__(16) __half g_Ah[(size_t)NPTS * DD];  /* 8 MB */
__device__ __align__(16) __half g_Bh[(size_t)KC * DD];    /* 512 KB */

extern __shared__ char smdyn[];

/* ---------------- helpers ---------------- */
__device__ __forceinline__ uint32_t smem_u32(const void* p) {
    uint32_t a;
    asm("{ .reg .u64 t; cvta.to.shared.u64 t, %1; cvt.u32.u64 %0, t; }" : "=r"(a) : "l"(p));
    return a;
}
__device__ __forceinline__ void ldm4(uint32_t* r, uint32_t addr) {
    asm volatile("ldmatrix.sync.aligned.m8n8.x4.shared.b16 {%0,%1,%2,%3}, [%4];"
        : "=r"(r[0]), "=r"(r[1]), "=r"(r[2]), "=r"(r[3]) : "r"(addr));
}
__device__ __forceinline__ void mma16816(float* c, const uint32_t* a, const uint32_t* b) {
    asm volatile("mma.sync.aligned.m16n8k16.row.col.f32.f16.f16.f32 "
        "{%0,%1,%2,%3}, {%4,%5,%6,%7}, {%8,%9}, {%0,%1,%2,%3};"
        : "+f"(c[0]), "+f"(c[1]), "+f"(c[2]), "+f"(c[3])
        : "r"(a[0]), "r"(a[1]), "r"(a[2]), "r"(a[3]), "r"(b[0]), "r"(b[1]));
}
__device__ __forceinline__ void cpa16(uint32_t dst, const void* src) {
    asm volatile("cp.async.cg.shared.global [%0], [%1], 16;" :: "r"(dst), "l"(src) : "memory");
}
/* combine two (min, second) pairs into one */
__device__ __forceinline__ void comb(uint32_t &r1, uint32_t &r2,
                                     uint32_t a1, uint32_t a2,
                                     uint32_t b1, uint32_t b2) {
    r1 = min(a1, b1);
    uint32_t t = max(a1, b1);
    r2 = min(min(a2, b2), t);
}

/* ------- prep: e2 (exact sequential fp32) + offset copy + fp16 B + scratch zero ------- */
__global__ __launch_bounds__(256) void k_prep_e(const float* __restrict__ emb) {
    int k = blockIdx.x * blockDim.x + threadIdx.x;
    if (k >= KC) return;
    g_counts[k] = 0;
    if (k == 0) { g_sqsum = 0.0f; g_flag_cnt = 0; }
    const float* row = emb + (size_t)k * DD;
    float s = 0.0f;
#pragma unroll
    for (int d = 0; d < DD; d++) s = __fadd_rn(s, __fmul_rn(row[d], row[d]));
    g_e2[k] = s;
    g_e2o[k] = s + YOFF;
    __half2* dst = (__half2*)(g_Bh + (size_t)k * DD);
#pragma unroll
    for (int d = 0; d < DD / 2; d++) dst[d] = __floats2half2_rn(row[2 * d], row[2 * d + 1]);
}
__global__ __launch_bounds__(256) void k_prep_z(const float* __restrict__ z) {
    int i = blockIdx.x * blockDim.x + threadIdx.x;     /* over N*D/2 */
    float2 v = ((const float2*)z)[i];
    ((__half2*)g_Ah)[i] = __floats2half2_rn(v.x, v.y);
}

/* ------- K2: fp16 HMMA proxy GEMM + key-packed tournament argmin + margin flag -------
 * proxy y'[n][k] = (e2[k]+YOFF) - 2*(zh[n].eh[k]) > 0; argmin invariant to +z2.
 * key = (bits(y') & ~0x1FF) | (c<<4 | nt<<1 | j); per-s tournament tree gives
 * exact (min, second) with index embedded in min. */
__global__ __launch_bounds__(256, 3)
void k_hmma() {
    char* sm = (char*)((((uintptr_t)smdyn) + 127) & ~(uintptr_t)127);
    const uint32_t smb = smem_u32(sm);
    const int tid = threadIdx.x;
    const int l   = tid & 31;
    const int wid = tid >> 5;
    const int m0  = (wid & 3) * 32;
    const int nb  = (wid >> 2) * 64;

    /* prologue: A tile + B chunk0 + e2o chunk0 via cp.async (pre-swizzled dst) */
    {
        const char* gA = (const char*)(g_Ah + (size_t)blockIdx.x * BM * DD);
#pragma unroll
        for (int i = 0; i < 4; i++) {
            int lin = tid + i * 256;                    /* 1024 x 16B */
            int row = lin >> 3, u = lin & 7;
            cpa16(smb + SA + row * 128 + ((u ^ (row & 7)) << 4), gA + lin * 16);
        }
#pragma unroll
        for (int i = 0; i < 4; i++) {
            int lin = tid + i * 256;
            int row = lin >> 3, u = lin & 7;
            cpa16(smb + SB0 + row * 128 + ((u ^ (row & 7)) << 4), (const char*)g_Bh + lin * 16);
        }
        if (tid < 32) cpa16(smb + SE0 + tid * 16, (const char*)g_e2o + tid * 16);
        asm volatile("cp.async.commit_group;" ::: "memory");
        asm volatile("cp.async.wait_group 0;" ::: "memory");
        __syncthreads();
    }

    /* cache A fragments: 2 m-tiles x 4 k-steps x 4 regs */
    uint32_t a[2][4][4];
#pragma unroll
    for (int mt = 0; mt < 2; mt++)
#pragma unroll
        for (int ks = 0; ks < 4; ks++) {
            int row = m0 + mt * 16 + (l & 7) + ((l >> 3) & 1) * 8;
            int u   = ks * 2 + (l >> 4);
            ldm4(a[mt][ks], smb + SA + row * 128 + ((u ^ (row & 7)) << 4));
        }

    uint32_t k1[4], k2[4];
#pragma unroll
    for (int s = 0; s < 4; s++) { k1[s] = 0xFFFFFFFFu; k2[s] = 0xFFFFFFFFu; }

    for (int c = 0; c < 32; c++) {
        const int cur = c & 1;
        __syncthreads();                                /* buf 1-cur free (chunk c-1 done) */
        if (c + 1 < 32) {
            const char* gB = (const char*)g_Bh + (size_t)(c + 1) * 16384;
            uint32_t bb = smb + (cur ? SB0 : SB1);
#pragma unroll
            for (int i = 0; i < 4; i++) {
                int lin = tid + i * 256;
                int row = lin >> 3, u = lin & 7;
                cpa16(bb + row * 128 + ((u ^ (row & 7)) << 4), gB + lin * 16);
            }
            if (tid < 32) cpa16(smb + (cur ? SE0 : SE1) + tid * 16,
                                (const char*)g_e2o + (c + 1) * 512 + tid * 16);
            asm volatile("cp.async.commit_group;" ::: "memory");
            asm volatile("cp.async.wait_group 1;" ::: "memory");
        } else {
            asm volatile("cp.async.wait_group 0;" ::: "memory");
        }
        __syncthreads();                                /* buf cur complete & visible */

        const uint32_t bbase = smb + (cur ? SB1 : SB0);
        const char*    ebase = sm + (cur ? SE1 : SE0);
        float e2v[8][2];
#pragma unroll
        for (int nt = 0; nt < 8; nt++)
#pragma unroll
            for (int j = 0; j < 2; j++)
                e2v[nt][j] = *(const float*)(ebase + (nb + nt * 8 + (l & 3) * 2 + j) * 4);

        float cc[2][8][4];
#pragma unroll
        for (int mt = 0; mt < 2; mt++)
#pragma unroll
            for (int nt = 0; nt < 8; nt++)
#pragma unroll
                for (int q = 0; q < 4; q++) cc[mt][nt][q] = 0.0f;

#pragma unroll
        for (int ks = 0; ks < 4; ks++) {
            uint32_t b[8][2];
#pragma unroll
            for (int g = 0; g < 4; g++) {
                int row = nb + g * 16 + (l & 7) + ((l >> 4) & 1) * 8;
                int u   = ks * 2 + ((l >> 3) & 1);
                uint32_t r4[4];
                ldm4(r4, bbase + row * 128 + ((u ^ (row & 7)) << 4));
                b[g * 2][0] = r4[0]; b[g * 2][1] = r4[1];
                b[g * 2 + 1][0] = r4[2]; b[g * 2 + 1][1] = r4[3];
            }
#pragma unroll
            for (int mt = 0; mt < 2; mt++)
#pragma unroll
                for (int nt = 0; nt < 8; nt++)
                    mma16816(cc[mt][nt], a[mt][ks], b[nt]);
        }

        /* key-packed tournament epilogue, per s-slot (exact min+second, index in min) */
        const uint32_t gb = (uint32_t)(c << 4);
#pragma unroll
        for (int mt = 0; mt < 2; mt++)
#pragma unroll
            for (int rh = 0; rh < 2; rh++) {
                const int s = mt * 2 + rh;
                uint32_t kv[16];
#pragma unroll
                for (int nt = 0; nt < 8; nt++)
#pragma unroll
                    for (int j = 0; j < 2; j++) {
                        float y = __fmaf_rn(-2.0f, cc[mt][nt][rh * 2 + j], e2v[nt][j]);
                        kv[nt * 2 + j] = (__float_as_uint(y) & 0xFFFFFE00u)
                                       | (gb + (uint32_t)(nt * 2 + j));
                    }
                uint32_t lo[8], hi[8];
#pragma unroll
                for (int p = 0; p < 8; p++) {
                    lo[p] = min(kv[2 * p], kv[2 * p + 1]);
                    hi[p] = max(kv[2 * p], kv[2 * p + 1]);
                }
                uint32_t q1[4], q2[4];
#pragma unroll
                for (int p = 0; p < 4; p++)
                    comb(q1[p], q2[p], lo[2 * p], hi[2 * p], lo[2 * p + 1], hi[2 * p + 1]);
                uint32_t r1a, r2a, r1b, r2b, f1, f2;
                comb(r1a, r2a, q1[0], q2[0], q1[1], q2[1]);
                comb(r1b, r2b, q1[2], q2[2], q1[3], q2[3]);
                comb(f1, f2, r1a, r2a, r1b, r2b);
                uint32_t t = min(f1, k1[s]);
                uint32_t u = max(f1, k1[s]);
                k2[s] = min(k2[s], min(f2, u));
                k1[s] = t;
            }
    }

    /* decode per-thread keys to (key64 with gid, margin float), reduce 4 lanes/row */
    u64   kk[4];
    float m2f[4];
#pragma unroll
    for (int s = 0; s < 4; s++) {
        uint32_t f = k1[s] & 0x1FFu;
        int gid = (int)(f >> 4) * 128 + nb + (int)(((f >> 1) & 7) << 3) + ((l & 3) << 1) + (int)(f & 1);
        kk[s] = ((u64)(k1[s] & 0xFFFFFE00u) << 32) | (unsigned)gid;
        m2f[s] = __uint_as_float(k2[s] & 0xFFFFFE00u);
    }
#pragma unroll
    for (int off = 1; off < 4; off <<= 1) {
#pragma unroll
        for (int s = 0; s < 4; s++) {
            u64   ok = __shfl_xor_sync(0xffffffffu, kk[s], off);
            float om = __shfl_xor_sync(0xffffffffu, m2f[s], off);
            u64 mx = (kk[s] > ok) ? kk[s] : ok;
            float ymx = __uint_as_float((uint32_t)(mx >> 32));
            m2f[s] = fminf(fminf(m2f[s], om), ymx);
            kk[s] = (kk[s] < ok) ? kk[s] : ok;
        }
    }

    /* merge col-halves (wn=0 vs wn=1) via smem (A region is dead now) */
    __syncthreads();
    u64*   mk = (u64*)sm;
    float* mm = (float*)(sm + 1024);
    if (wid >= 4 && (l & 3) == 0) {
#pragma unroll
        for (int s = 0; s < 4; s++) {
            int r = m0 + (s >> 1) * 16 + (s & 1) * 8 + (l >> 2);
            mk[r] = kk[s]; mm[r] = m2f[s];
        }
    }
    __syncthreads();
    if (wid < 4 && (l & 3) == 0) {
#pragma unroll
        for (int s = 0; s < 4; s++) {
            int r = m0 + (s >> 1) * 16 + (s & 1) * 8 + (l >> 2);
            u64 ok = mk[r]; float om = mm[r];
            u64 mx = (kk[s] > ok) ? kk[s] : ok;
            float ymx = __uint_as_float((uint32_t)(mx >> 32));
            float msec = fminf(fminf(m2f[s], om), ymx);
            u64 kmin = (kk[s] < ok) ? kk[s] : ok;
            int row = blockIdx.x * BM + r;
            g_idx[row] = (int)(kmin & 0xFFFFFFFFULL);
            float b1f = __uint_as_float((uint32_t)(kmin >> 32));
            if (msec - b1f < THETA_FLAG) {
                int p = atomicAdd(&g_flag_cnt, 1);
                g_flag_list[p] = row;
                g_b1f[p] = b1f;
                g_ccnt[p] = 0;
            }
        }
    }
}

/* ------- K3a: candidate collection for flagged rows (HMMA proxy re-run) ------- */
__global__ __launch_bounds__(256)
void k_cand() {
    char* sm = (char*)((((uintptr_t)smdyn) + 127) & ~(uintptr_t)127);
    const uint32_t smb = smem_u32(sm);
    __shared__ int   rl[BM];
    __shared__ float b1t[BM];
    const int tid = threadIdx.x;
    const int l   = tid & 31;
    const int wid = tid >> 5;
    const int m0  = (wid & 3) * 32;
    const int nb  = (wid >> 2) * 64;
    const int cnt = g_flag_cnt;
    const int cbeg = blockIdx.y * 4;                   /* 4 chunks per K-split (8 splits) */

    for (int tile = blockIdx.x; tile * BM < cnt; tile += gridDim.x) {
        const int n0 = tile * BM;
        const int nrows = min(BM, cnt - n0);
        if (tid < BM) {
            rl[tid]  = g_flag_list[n0 + min(tid, nrows - 1)];
            b1t[tid] = (tid < nrows) ? (g_b1f[n0 + tid] + THETA_CAND) : -3.4e38f;
        }
        __syncthreads();

        /* gather A rows */
#pragma unroll
        for (int i = 0; i < 4; i++) {
            int lin = tid + i * 256;
            int row = lin >> 3, u = lin & 7;
            cpa16(smb + SA + row * 128 + ((u ^ (row & 7)) << 4),
                  (const char*)(g_Ah + (size_t)rl[row] * DD) + u * 16);
        }
        /* first B chunk + e2o */
        {
            const char* gB = (const char*)g_Bh + (size_t)cbeg * 16384;
#pragma unroll
            for (int i = 0; i < 4; i++) {
                int lin = tid + i * 256;
                int row = lin >> 3, u = lin & 7;
                cpa16(smb + SB0 + row * 128 + ((u ^ (row & 7)) << 4), gB + lin * 16);
            }
            if (tid < 32) cpa16(smb + SE0 + tid * 16, (const char*)g_e2o + cbeg * 512 + tid * 16);
        }
        asm volatile("cp.async.commit_group;" ::: "memory");
        asm volatile("cp.async.wait_group 0;" ::: "memory");
        __syncthreads();

        uint32_t a[2][4][4];
#pragma unroll
        for (int mt = 0; mt < 2; mt++)
#pragma unroll
            for (int ks = 0; ks < 4; ks++) {
                int row = m0 + mt * 16 + (l & 7) + ((l >> 3) & 1) * 8;
                int u   = ks * 2 + (l >> 4);
                ldm4(a[mt][ks], smb + SA + row * 128 + ((u ^ (row & 7)) << 4));
            }
        float b1r[4];
#pragma unroll
        for (int s = 0; s < 4; s++)
            b1r[s] = b1t[m0 + (s >> 1) * 16 + (s & 1) * 8 + (l >> 2)];

        for (int ci = 0; ci < 4; ci++) {
            const int c = cbeg + ci;
            const int cur = ci & 1;
            __syncthreads();
            if (ci + 1 < 4) {
                const char* gB = (const char*)g_Bh + (size_t)(c + 1) * 16384;
                uint32_t bb = smb + (cur ? SB0 : SB1);
#pragma unroll
                for (int i = 0; i < 4; i++) {
                    int lin = tid + i * 256;
                    int row = lin >> 3, u = lin & 7;
                    cpa16(bb + row * 128 + ((u ^ (row & 7)) << 4), gB + lin * 16);
                }
                if (tid < 32) cpa16(smb + (cur ? SE0 : SE1) + tid * 16,
                                    (const char*)g_e2o + (c + 1) * 512 + tid * 16);
                asm volatile("cp.async.commit_group;" ::: "memory");
                asm volatile("cp.async.wait_group 1;" ::: "memory");
            } else {
                asm volatile("cp.async.wait_group 0;" ::: "memory");
            }
            __syncthreads();

            const uint32_t bbase = smb + (cur ? SB1 : SB0);
            const char*    ebase = sm + (cur ? SE1 : SE0);
            float e2v[8][2];
#pragma unroll
            for (int nt = 0; nt < 8; nt++)
#pragma unroll
                for (int j = 0; j < 2; j++)
                    e2v[nt][j] = *(const float*)(ebase + (nb + nt * 8 + (l & 3) * 2 + j) * 4);

            float cc[2][8][4];
#pragma unroll
            for (int mt = 0; mt < 2; mt++)
#pragma unroll
                for (int nt = 0; nt < 8; nt++)
#pragma unroll
                    for (int q = 0; q < 4; q++) cc[mt][nt][q] = 0.0f;

#pragma unroll
            for (int ks = 0; ks < 4; ks++) {
                uint32_t b[8][2];
#pragma unroll
                for (int g = 0; g < 4; g++) {
                    int row = nb + g * 16 + (l & 7) + ((l >> 4) & 1) * 8;
                    int u   = ks * 2 + ((l >> 3) & 1);
                    uint32_t r4[4];
                    ldm4(r4, bbase + row * 128 + ((u ^ (row & 7)) << 4));
                    b[g * 2][0] = r4[0]; b[g * 2][1] = r4[1];
                    b[g * 2 + 1][0] = r4[2]; b[g * 2 + 1][1] = r4[3];
                }
#pragma unroll
                for (int mt = 0; mt < 2; mt++)
#pragma unroll
                    for (int nt = 0; nt < 8; nt++)
                        mma16816(cc[mt][nt], a[mt][ks], b[nt]);
            }

            const int gb0 = c * BN + nb + (l & 3) * 2;
#pragma unroll
            for (int mt = 0; mt < 2; mt++)
#pragma unroll
                for (int nt = 0; nt < 8; nt++)
#pragma unroll
                    for (int rh = 0; rh < 2; rh++)
#pragma unroll
                        for (int j = 0; j < 2; j++) {
                            float y = __fmaf_rn(-2.0f, cc[mt][nt][rh * 2 + j], e2v[nt][j]);
                            int s = mt * 2 + rh;
                            if (y <= b1r[s]) {
                                int r = m0 + mt * 16 + rh * 8 + (l >> 2);
                                int fi = n0 + r;
                                int slot = atomicAdd(&g_ccnt[fi], 1);
                                if (slot < CCAP)
                                    g_cand[(size_t)fi * CCAP + slot] = gb0 + nt * 8 + j;
                            }
                        }
        }
        __syncthreads();
    }
}

/* ------- K3b: exact scoring of candidates (bit-exact round-3 formula) ------- */
__global__ __launch_bounds__(256)
void k_exact(const float* __restrict__ z, const float* __restrict__ emb) {
    const int cnt = g_flag_cnt;
    for (int p = blockIdx.x * blockDim.x + threadIdx.x; p < cnt;
         p += gridDim.x * blockDim.x) {
        int row = g_flag_list[p];
        const float* zr = z + (size_t)row * DD;
        float z2 = 0.0f;
#pragma unroll
        for (int d = 0; d < DD; d++) z2 = __fadd_rn(z2, __fmul_rn(zr[d], zr[d]));

        int nc = g_ccnt[p];
        float best = 3.4e38f; int bi = 0x7FFFFFFF;
        if (nc <= CCAP) {
            for (int q = 0; q < nc; q++) {
                int c = g_cand[(size_t)p * CCAP + q];
                const float* er = emb + (size_t)c * DD;
                float s = 0.0f;
#pragma unroll
                for (int d = 0; d < DD; d++) s = __fmaf_rn(zr[d], er[d], s);
                float x = __fsub_rn(__fadd_rn(z2, g_e2[c]), __fmul_rn(2.0f, s));
                if (x < best || (x == best && c < bi)) { best = x; bi = c; }
            }
        } else {                                       /* overflow: full scan */
            for (int c = 0; c < KC; c++) {
                const float* er = emb + (size_t)c * DD;
                float s = 0.0f;
#pragma unroll
                for (int d = 0; d < DD; d++) s = __fmaf_rn(zr[d], er[d], s);
                float x = __fsub_rn(__fadd_rn(z2, g_e2[c]), __fmul_rn(2.0f, s));
                if (x < best || (x == best && c < bi)) { best = x; bi = c; }
            }
        }
        g_idx[row] = bi;
    }
}

/* ------- K4: gather z_q, losses, counts (512 blocks x 128 rows) ------- */
__global__ __launch_bounds__(256)
void k_gather(const float* __restrict__ z, const float* __restrict__ emb,
              float* __restrict__ out) {
    __shared__ float red[256];
    const int tid  = threadIdx.x;
    const int base = blockIdx.x * 128;
    float acc = 0.0f;
    const size_t ND = (size_t)NPTS * DD;

#pragma unroll
    for (int i = 0; i < 8; i++) {
        int lin = tid + i * 256;                        /* 128 rows x 16 float4 */
        int r = lin >> 4, d4 = lin & 15;
        int n = base + r;
        int idx = g_idx[n];
        float4 e4 = *reinterpret_cast<const float4*>(emb + (size_t)idx * DD + d4 * 4);
        float4 z4 = *reinterpret_cast<const float4*>(z + (size_t)n * DD + d4 * 4);
        *reinterpret_cast<float4*>(out + (size_t)n * DD + d4 * 4) = e4;
        float dx = e4.x - z4.x, dy = e4.y - z4.y, dz = e4.z - z4.z, dw = e4.w - z4.w;
        acc += dx * dx + dy * dy + dz * dz + dw * dw;
        if (d4 == 0) {
            atomicAdd(&g_counts[idx], 1);
            out[ND + 3 + n] = (float)idx;
        }
    }
    red[tid] = acc;
    __syncthreads();
    for (int s = 128; s > 0; s >>= 1) {
        if (tid < s) red[tid] += red[tid + s];
        __syncthreads();
    }
    if (tid == 0) atomicAdd(&g_sqsum, red[0]);
}

__global__ void k_final(float* __restrict__ out) {
    __shared__ float sH[256];
    __shared__ int   sA[256];
    int tid = threadIdx.x;
    float H = 0.0f; int active = 0;
    for (int i = tid; i < KC; i += 256) {
        float p = (float)g_counts[i] * (1.0f / 65536.0f);
        H += p * logf(p + 1e-10f);
        if (p > 0.0f) active++;
    }
    sH[tid] = H; sA[tid] = active;
    __syncthreads();
    for (int s = 128; s > 0; s >>= 1) {
        if (tid < s) { sH[tid] += sH[tid + s]; sA[tid] += sA[tid + s]; }
        __syncthreads();
    }
    if (tid == 0) {
        const size_t ND = (size_t)NPTS * DD;
        float mse = g_sqsum / (float)(NPTS * DD);
        out[ND]     = __fadd_rn(mse, __fmul_rn(0.25f, mse));
        out[ND + 1] = mse;
        out[ND + 2] = mse;
        out[ND + 3 + NPTS] = expf(-sH[0]);
        out[ND + 4 + NPTS] = (float)sA[0];
    }
}

extern "C" void kernel_launch(void* const* d_in, const int* in_sizes, int n_in,
                              void* d_out, int out_size) {
    const float *z, *emb;
    if (in_sizes[0] == KC * DD) { emb = (const float*)d_in[0]; z = (const float*)d_in[1]; }
    else                        { z   = (const float*)d_in[0]; emb = (const float*)d_in[1]; }
    float* out = (float*)d_out;

    cudaFuncSetAttribute(k_hmma, cudaFuncAttributeMaxDynamicSharedMemorySize, SMEM_H);
    cudaFuncSetAttribute(k_cand, cudaFuncAttributeMaxDynamicSharedMemorySize, SMEM_H);

    k_prep_e<<<16, 256>>>(emb);
    k_prep_z<<<(NPTS * DD / 2) / 256, 256>>>(z);
    k_hmma  <<<NPTS / BM, 256, SMEM_H>>>();
    k_cand  <<<dim3(64, 8), 256, SMEM_H>>>();
    k_exact <<<64, 256>>>(z, emb);
    k_gather<<<512, 256>>>(z, emb, out);
    k_final <<<1, 256>>>(out);
}

// round 16
// speedup vs baseline: 1.7881x; 1.7881x over previous
#include <cuda_runtime.h>
#include <cuda_fp16.h>
#include <math.h>
#include <stdint.h>

typedef unsigned long long u64;

#define NPTS 65536
#define KC   4096
#define DD   64
#define BM   128
#define BN   128
#define NTHREADS 256
#define THETA 3e-5f
#define CCAP 16

/* k_hmma/k_cand smem offsets (from 128B-aligned base) */
#define SA   0          /* A tile: 128 rows x 128B (swizzled); reused as merge space */
#define SB0  16384
#define SB1  32768
#define SE0  49152      /* e2 chunk: 128 floats */
#define SE1  49664
#define SMEM_H (50176 + 128)

/* ---------------- device scratch ---------------- */
__device__ float g_e2[KC];
__device__ int   g_counts[KC];
__device__ float g_sqsum;
__device__ int   g_idx[NPTS];
__device__ int   g_flag_cnt;
__device__ int   g_flag_list[NPTS];
__device__ float g_b1f[NPTS];
__device__ int   g_ccnt[NPTS];
__device__ int   g_cand[(size_t)NPTS * CCAP];             /* 4 MB */
__device__ __align__(16) __half g_Ah[(size_t)NPTS * DD];  /* 8 MB */
__device__ __align__(16) __half g_Bh[(size_t)KC * DD];    /* 512 KB */

extern __shared__ char smdyn[];

/* ---------------- helpers ---------------- */
__device__ __forceinline__ uint32_t smem_u32(const void* p) {
    uint32_t a;
    asm("{ .reg .u64 t; cvta.to.shared.u64 t, %1; cvt.u32.u64 %0, t; }" : "=r"(a) : "l"(p));
    return a;
}
__device__ __forceinline__ void ldm4(uint32_t* r, uint32_t addr) {
    asm volatile("ldmatrix.sync.aligned.m8n8.x4.shared.b16 {%0,%1,%2,%3}, [%4];"
        : "=r"(r[0]), "=r"(r[1]), "=r"(r[2]), "=r"(r[3]) : "r"(addr));
}
__device__ __forceinline__ void mma16816(float* c, const uint32_t* a, const uint32_t* b) {
    asm volatile("mma.sync.aligned.m16n8k16.row.col.f32.f16.f16.f32 "
        "{%0,%1,%2,%3}, {%4,%5,%6,%7}, {%8,%9}, {%0,%1,%2,%3};"
        : "+f"(c[0]), "+f"(c[1]), "+f"(c[2]), "+f"(c[3])
        : "r"(a[0]), "r"(a[1]), "r"(a[2]), "r"(a[3]), "r"(b[0]), "r"(b[1]));
}
__device__ __forceinline__ void cpa16(uint32_t dst, const void* src) {
    asm volatile("cp.async.cg.shared.global [%0], [%1], 16;" :: "r"(dst), "l"(src) : "memory");
}

/* ------- prep (merged): e2 + fp16 B + scratch zero (blocks 0-15), fp16 A (rest) ------- */
__global__ __launch_bounds__(256) void k_prep(const float* __restrict__ emb,
                                              const float* __restrict__ z) {
    if (blockIdx.x < 16) {
        int k = blockIdx.x * 256 + threadIdx.x;
        g_counts[k] = 0;
        if (k == 0) { g_sqsum = 0.0f; g_flag_cnt = 0; }
        const float* row = emb + (size_t)k * DD;
        float s = 0.0f;
#pragma unroll
        for (int d = 0; d < DD; d++) s = __fadd_rn(s, __fmul_rn(row[d], row[d]));
        g_e2[k] = s;
        __half2* dst = (__half2*)(g_Bh + (size_t)k * DD);
#pragma unroll
        for (int d = 0; d < DD / 2; d++) dst[d] = __floats2half2_rn(row[2 * d], row[2 * d + 1]);
    } else {
        int i = (blockIdx.x - 16) * 256 + threadIdx.x;  /* over N*D/2 */
        float2 v = ((const float2*)z)[i];
        ((__half2*)g_Ah)[i] = __floats2half2_rn(v.x, v.y);
    }
}

/* ------- K2: fp16 HMMA distance-proxy GEMM + running argmin + margin flag -------
 * (round-14 proven version; only delta: launch_bounds minBlocks=3 for occupancy) */
__global__ __launch_bounds__(256, 3)
void k_hmma() {
    char* sm = (char*)((((uintptr_t)smdyn) + 127) & ~(uintptr_t)127);
    const uint32_t smb = smem_u32(sm);
    const int tid = threadIdx.x;
    const int l   = tid & 31;
    const int wid = tid >> 5;
    const int m0  = (wid & 3) * 32;
    const int nb  = (wid >> 2) * 64;

    /* prologue: A tile + B chunk0 + e2 chunk0 via cp.async (pre-swizzled dst) */
    {
        const char* gA = (const char*)(g_Ah + (size_t)blockIdx.x * BM * DD);
#pragma unroll
        for (int i = 0; i < 4; i++) {
            int lin = tid + i * 256;                    /* 1024 x 16B */
            int row = lin >> 3, u = lin & 7;
            cpa16(smb + SA + row * 128 + ((u ^ (row & 7)) << 4), gA + lin * 16);
        }
#pragma unroll
        for (int i = 0; i < 4; i++) {
            int lin = tid + i * 256;
            int row = lin >> 3, u = lin & 7;
            cpa16(smb + SB0 + row * 128 + ((u ^ (row & 7)) << 4), (const char*)g_Bh + lin * 16);
        }
        if (tid < 32) cpa16(smb + SE0 + tid * 16, (const char*)g_e2 + tid * 16);
        asm volatile("cp.async.commit_group;" ::: "memory");
        asm volatile("cp.async.wait_group 0;" ::: "memory");
        __syncthreads();
    }

    /* cache A fragments: 2 m-tiles x 4 k-steps x 4 regs */
    uint32_t a[2][4][4];
#pragma unroll
    for (int mt = 0; mt < 2; mt++)
#pragma unroll
        for (int ks = 0; ks < 4; ks++) {
            int row = m0 + mt * 16 + (l & 7) + ((l >> 3) & 1) * 8;
            int u   = ks * 2 + (l >> 4);
            ldm4(a[mt][ks], smb + SA + row * 128 + ((u ^ (row & 7)) << 4));
        }

    float b1[4], b2[4]; int i1[4];
#pragma unroll
    for (int s = 0; s < 4; s++) { b1[s] = 3.4e38f; b2[s] = 3.4e38f; i1[s] = 0; }

    for (int c = 0; c < 32; c++) {
        const int cur = c & 1;
        __syncthreads();                                /* buf 1-cur free (chunk c-1 done) */
        if (c + 1 < 32) {
            const char* gB = (const char*)g_Bh + (size_t)(c + 1) * 16384;
            uint32_t bb = smb + (cur ? SB0 : SB1);
#pragma unroll
            for (int i = 0; i < 4; i++) {
                int lin = tid + i * 256;
                int row = lin >> 3, u = lin & 7;
                cpa16(bb + row * 128 + ((u ^ (row & 7)) << 4), gB + lin * 16);
            }
            if (tid < 32) cpa16(smb + (cur ? SE0 : SE1) + tid * 16,
                                (const char*)g_e2 + (c + 1) * 512 + tid * 16);
            asm volatile("cp.async.commit_group;" ::: "memory");
            asm volatile("cp.async.wait_group 1;" ::: "memory");
        } else {
            asm volatile("cp.async.wait_group 0;" ::: "memory");
        }
        __syncthreads();                                /* buf cur complete & visible */

        const uint32_t bbase = smb + (cur ? SB1 : SB0);
        const char*    ebase = sm + (cur ? SE1 : SE0);
        float e2v[8][2];
#pragma unroll
        for (int nt = 0; nt < 8; nt++)
#pragma unroll
            for (int j = 0; j < 2; j++)
                e2v[nt][j] = *(const float*)(ebase + (nb + nt * 8 + (l & 3) * 2 + j) * 4);

        float cc[2][8][4];
#pragma unroll
        for (int mt = 0; mt < 2; mt++)
#pragma unroll
            for (int nt = 0; nt < 8; nt++)
#pragma unroll
                for (int q = 0; q < 4; q++) cc[mt][nt][q] = 0.0f;

#pragma unroll
        for (int ks = 0; ks < 4; ks++) {
            uint32_t b[8][2];
#pragma unroll
            for (int g = 0; g < 4; g++) {
                int row = nb + g * 16 + (l & 7) + ((l >> 4) & 1) * 8;
                int u   = ks * 2 + ((l >> 3) & 1);
                uint32_t r4[4];
                ldm4(r4, bbase + row * 128 + ((u ^ (row & 7)) << 4));
                b[g * 2][0] = r4[0]; b[g * 2][1] = r4[1];
                b[g * 2 + 1][0] = r4[2]; b[g * 2 + 1][1] = r4[3];
            }
#pragma unroll
            for (int mt = 0; mt < 2; mt++)
#pragma unroll
                for (int nt = 0; nt < 8; nt++)
                    mma16816(cc[mt][nt], a[mt][ks], b[nt]);
        }

        const int gb0 = c * BN + nb + (l & 3) * 2;
#pragma unroll
        for (int mt = 0; mt < 2; mt++)
#pragma unroll
            for (int nt = 0; nt < 8; nt++)
#pragma unroll
                for (int rh = 0; rh < 2; rh++)
#pragma unroll
                    for (int j = 0; j < 2; j++) {
                        float y = __fmaf_rn(-2.0f, cc[mt][nt][rh * 2 + j], e2v[nt][j]);
                        int s = mt * 2 + rh;
                        int gid = gb0 + nt * 8 + j;
                        bool lt = y < b1[s];
                        b2[s] = fminf(b2[s], lt ? b1[s] : y);
                        if (lt) { b1[s] = y; i1[s] = gid; }
                    }
    }

    /* reduce 4 lanes sharing each row (xor over low 2 bits of lane) */
#pragma unroll
    for (int off = 1; off < 4; off <<= 1) {
#pragma unroll
        for (int s = 0; s < 4; s++) {
            float ob1 = __shfl_xor_sync(0xffffffffu, b1[s], off);
            float ob2 = __shfl_xor_sync(0xffffffffu, b2[s], off);
            int   oi  = __shfl_xor_sync(0xffffffffu, i1[s], off);
            float hi = fmaxf(b1[s], ob1);
            b2[s] = fminf(fminf(b2[s], ob2), hi);
            if (ob1 < b1[s] || (ob1 == b1[s] && oi < i1[s])) { b1[s] = ob1; i1[s] = oi; }
        }
    }

    /* merge col-halves (wn=0 vs wn=1) via smem (A region is dead now) */
    __syncthreads();
    float* m1 = (float*)sm;
    float* m2 = m1 + 128;
    int*   mi = (int*)(m2 + 128);
    if (wid >= 4 && (l & 3) == 0) {
#pragma unroll
        for (int s = 0; s < 4; s++) {
            int r = m0 + (s >> 1) * 16 + (s & 1) * 8 + (l >> 2);
            m1[r] = b1[s]; m2[r] = b2[s]; mi[r] = i1[s];
        }
    }
    __syncthreads();
    if (wid < 4 && (l & 3) == 0) {
#pragma unroll
        for (int s = 0; s < 4; s++) {
            int r = m0 + (s >> 1) * 16 + (s & 1) * 8 + (l >> 2);
            float ob1 = m1[r], ob2 = m2[r]; int oi = mi[r];
            float hi = fmaxf(b1[s], ob1);
            float nb2 = fminf(fminf(b2[s], ob2), hi);
            float nb1 = b1[s]; int ni = i1[s];
            if (ob1 < nb1 || (ob1 == nb1 && oi < ni)) { nb1 = ob1; ni = oi; }
            int row = blockIdx.x * BM + r;
            g_idx[row] = ni;
            if (nb2 - nb1 < THETA) {
                int p = atomicAdd(&g_flag_cnt, 1);
                g_flag_list[p] = row;
                g_b1f[p] = nb1;
                g_ccnt[p] = 0;
            }
        }
    }
}

/* ------- K3a: candidate collection for flagged rows (HMMA proxy re-run) -------
 * Same GEMM mapping as k_hmma, A rows gathered via flag list. Appends every
 * code with y <= b1+THETA (always includes the proxy winner). */
__global__ __launch_bounds__(256)
void k_cand() {
    char* sm = (char*)((((uintptr_t)smdyn) + 127) & ~(uintptr_t)127);
    const uint32_t smb = smem_u32(sm);
    __shared__ int   rl[BM];
    __shared__ float b1t[BM];
    const int tid = threadIdx.x;
    const int l   = tid & 31;
    const int wid = tid >> 5;
    const int m0  = (wid & 3) * 32;
    const int nb  = (wid >> 2) * 64;
    const int cnt = g_flag_cnt;
    const int cbeg = blockIdx.y * 8;                   /* 8 chunks per K-split */

    for (int tile = blockIdx.x; tile * BM < cnt; tile += gridDim.x) {
        const int n0 = tile * BM;
        const int nrows = min(BM, cnt - n0);
        if (tid < BM) {
            rl[tid]  = g_flag_list[n0 + min(tid, nrows - 1)];
            b1t[tid] = (tid < nrows) ? (g_b1f[n0 + tid] + THETA) : -3.4e38f;
        }
        __syncthreads();

        /* gather A rows */
#pragma unroll
        for (int i = 0; i < 4; i++) {
            int lin = tid + i * 256;
            int row = lin >> 3, u = lin & 7;
            cpa16(smb + SA + row * 128 + ((u ^ (row & 7)) << 4),
                  (const char*)(g_Ah + (size_t)rl[row] * DD) + u * 16);
        }
        /* first B chunk + e2 */
        {
            const char* gB = (const char*)g_Bh + (size_t)cbeg * 16384;
#pragma unroll
            for (int i = 0; i < 4; i++) {
                int lin = tid + i * 256;
                int row = lin >> 3, u = lin & 7;
                cpa16(smb + SB0 + row * 128 + ((u ^ (row & 7)) << 4), gB + lin * 16);
            }
            if (tid < 32) cpa16(smb + SE0 + tid * 16, (const char*)g_e2 + cbeg * 512 + tid * 16);
        }
        asm volatile("cp.async.commit_group;" ::: "memory");
        asm volatile("cp.async.wait_group 0;" ::: "memory");
        __syncthreads();

        uint32_t a[2][4][4];
#pragma unroll
        for (int mt = 0; mt < 2; mt++)
#pragma unroll
            for (int ks = 0; ks < 4; ks++) {
                int row = m0 + mt * 16 + (l & 7) + ((l >> 3) & 1) * 8;
                int u   = ks * 2 + (l >> 4);
                ldm4(a[mt][ks], smb + SA + row * 128 + ((u ^ (row & 7)) << 4));
            }
        float b1r[4];
#pragma unroll
        for (int s = 0; s < 4; s++)
            b1r[s] = b1t[m0 + (s >> 1) * 16 + (s & 1) * 8 + (l >> 2)];

        for (int ci = 0; ci < 8; ci++) {
            const int c = cbeg + ci;
            const int cur = ci & 1;
            __syncthreads();
            if (ci + 1 < 8) {
                const char* gB = (const char*)g_Bh + (size_t)(c + 1) * 16384;
                uint32_t bb = smb + (cur ? SB0 : SB1);
#pragma unroll
                for (int i = 0; i < 4; i++) {
                    int lin = tid + i * 256;
                    int row = lin >> 3, u = lin & 7;
                    cpa16(bb + row * 128 + ((u ^ (row & 7)) << 4), gB + lin * 16);
                }
                if (tid < 32) cpa16(smb + (cur ? SE0 : SE1) + tid * 16,
                                    (const char*)g_e2 + (c + 1) * 512 + tid * 16);
                asm volatile("cp.async.commit_group;" ::: "memory");
                asm volatile("cp.async.wait_group 1;" ::: "memory");
            } else {
                asm volatile("cp.async.wait_group 0;" ::: "memory");
            }
            __syncthreads();

            const uint32_t bbase = smb + (cur ? SB1 : SB0);
            const char*    ebase = sm + (cur ? SE1 : SE0);
            float e2v[8][2];
#pragma unroll
            for (int nt = 0; nt < 8; nt++)
#pragma unroll
                for (int j = 0; j < 2; j++)
                    e2v[nt][j] = *(const float*)(ebase + (nb + nt * 8 + (l & 3) * 2 + j) * 4);

            float cc[2][8][4];
#pragma unroll
            for (int mt = 0; mt < 2; mt++)
#pragma unroll
                for (int nt = 0; nt < 8; nt++)
#pragma unroll
                    for (int q = 0; q < 4; q++) cc[mt][nt][q] = 0.0f;

#pragma unroll
            for (int ks = 0; ks < 4; ks++) {
                uint32_t b[8][2];
#pragma unroll
                for (int g = 0; g < 4; g++) {
                    int row = nb + g * 16 + (l & 7) + ((l >> 4) & 1) * 8;
                    int u   = ks * 2 + ((l >> 3) & 1);
                    uint32_t r4[4];
                    ldm4(r4, bbase + row * 128 + ((u ^ (row & 7)) << 4));
                    b[g * 2][0] = r4[0]; b[g * 2][1] = r4[1];
                    b[g * 2 + 1][0] = r4[2]; b[g * 2 + 1][1] = r4[3];
                }
#pragma unroll
                for (int mt = 0; mt < 2; mt++)
#pragma unroll
                    for (int nt = 0; nt < 8; nt++)
                        mma16816(cc[mt][nt], a[mt][ks], b[nt]);
            }

            const int gb0 = c * BN + nb + (l & 3) * 2;
#pragma unroll
            for (int mt = 0; mt < 2; mt++)
#pragma unroll
                for (int nt = 0; nt < 8; nt++)
#pragma unroll
                    for (int rh = 0; rh < 2; rh++)
#pragma unroll
                        for (int j = 0; j < 2; j++) {
                            float y = __fmaf_rn(-2.0f, cc[mt][nt][rh * 2 + j], e2v[nt][j]);
                            int s = mt * 2 + rh;
                            if (y <= b1r[s]) {
                                int r = m0 + mt * 16 + rh * 8 + (l >> 2);
                                int fi = n0 + r;
                                int slot = atomicAdd(&g_ccnt[fi], 1);
                                if (slot < CCAP)
                                    g_cand[(size_t)fi * CCAP + slot] = gb0 + nt * 8 + j;
                            }
                        }
        }
        __syncthreads();
    }
}

/* ------- K3b: exact scoring of candidates (bit-exact round-3 formula) ------- */
__global__ __launch_bounds__(256)
void k_exact(const float* __restrict__ z, const float* __restrict__ emb) {
    const int cnt = g_flag_cnt;
    for (int p = blockIdx.x * blockDim.x + threadIdx.x; p < cnt;
         p += gridDim.x * blockDim.x) {
        int row = g_flag_list[p];
        const float* zr = z + (size_t)row * DD;
        float z2 = 0.0f;
#pragma unroll
        for (int d = 0; d < DD; d++) z2 = __fadd_rn(z2, __fmul_rn(zr[d], zr[d]));

        int nc = g_ccnt[p];
        float best = 3.4e38f; int bi = 0x7FFFFFFF;
        if (nc <= CCAP) {
            for (int q = 0; q < nc; q++) {
                int c = g_cand[(size_t)p * CCAP + q];
                const float* er = emb + (size_t)c * DD;
                float s = 0.0f;
#pragma unroll
                for (int d = 0; d < DD; d++) s = __fmaf_rn(zr[d], er[d], s);
                float x = __fsub_rn(__fadd_rn(z2, g_e2[c]), __fmul_rn(2.0f, s));
                if (x < best || (x == best && c < bi)) { best = x; bi = c; }
            }
        } else {                                       /* overflow: full scan */
            for (int c = 0; c < KC; c++) {
                const float* er = emb + (size_t)c * DD;
                float s = 0.0f;
#pragma unroll
                for (int d = 0; d < DD; d++) s = __fmaf_rn(zr[d], er[d], s);
                float x = __fsub_rn(__fadd_rn(z2, g_e2[c]), __fmul_rn(2.0f, s));
                if (x < best || (x == best && c < bi)) { best = x; bi = c; }
            }
        }
        g_idx[row] = bi;
    }
}

/* ------- K4: gather z_q, losses, counts (512 blocks x 128 rows) ------- */
__global__ __launch_bounds__(256)
void k_gather(const float* __restrict__ z, const float* __restrict__ emb,
              float* __restrict__ out) {
    __shared__ float red[256];
    const int tid  = threadIdx.x;
    const int base = blockIdx.x * 128;
    float acc = 0.0f;
    const size_t ND = (size_t)NPTS * DD;

#pragma unroll
    for (int i = 0; i < 8; i++) {
        int lin = tid + i * 256;                        /* 128 rows x 16 float4 */
        int r = lin >> 4, d4 = lin & 15;
        int n = base + r;
        int idx = g_idx[n];
        float4 e4 = *reinterpret_cast<const float4*>(emb + (size_t)idx * DD + d4 * 4);
        float4 z4 = *reinterpret_cast<const float4*>(z + (size_t)n * DD + d4 * 4);
        *reinterpret_cast<float4*>(out + (size_t)n * DD + d4 * 4) = e4;
        float dx = e4.x - z4.x, dy = e4.y - z4.y, dz = e4.z - z4.z, dw = e4.w - z4.w;
        acc += dx * dx + dy * dy + dz * dz + dw * dw;
        if (d4 == 0) {
            atomicAdd(&g_counts[idx], 1);
            out[ND + 3 + n] = (float)idx;
        }
    }
    red[tid] = acc;
    __syncthreads();
    for (int s = 128; s > 0; s >>= 1) {
        if (tid < s) red[tid] += red[tid + s];
        __syncthreads();
    }
    if (tid == 0) atomicAdd(&g_sqsum, red[0]);
}

__global__ void k_final(float* __restrict__ out) {
    __shared__ float sH[256];
    __shared__ int   sA[256];
    int tid = threadIdx.x;
    float H = 0.0f; int active = 0;
    for (int i = tid; i < KC; i += 256) {
        float p = (float)g_counts[i] * (1.0f / 65536.0f);
        H += p * logf(p + 1e-10f);
        if (p > 0.0f) active++;
    }
    sH[tid] = H; sA[tid] = active;
    __syncthreads();
    for (int s = 128; s > 0; s >>= 1) {
        if (tid < s) { sH[tid] += sH[tid + s]; sA[tid] += sA[tid + s]; }
        __syncthreads();
    }
    if (tid == 0) {
        const size_t ND = (size_t)NPTS * DD;
        float mse = g_sqsum / (float)(NPTS * DD);
        out[ND]     = __fadd_rn(mse, __fmul_rn(0.25f, mse));
        out[ND + 1] = mse;
        out[ND + 2] = mse;
        out[ND + 3 + NPTS] = expf(-sH[0]);
        out[ND + 4 + NPTS] = (float)sA[0];
    }
}

extern "C" void kernel_launch(void* const* d_in, const int* in_sizes, int n_in,
                              void* d_out, int out_size) {
    const float *z, *emb;
    if (in_sizes[0] == KC * DD) { emb = (const float*)d_in[0]; z = (const float*)d_in[1]; }
    else                        { z   = (const float*)d_in[0]; emb = (const float*)d_in[1]; }
    float* out = (float*)d_out;

    cudaFuncSetAttribute(k_hmma, cudaFuncAttributeMaxDynamicSharedMemorySize, SMEM_H);
    cudaFuncSetAttribute(k_cand, cudaFuncAttributeMaxDynamicSharedMemorySize, SMEM_H);

    k_prep  <<<16 + (NPTS * DD / 2) / 256, 256>>>(emb, z);
    k_hmma  <<<NPTS / BM, 256, SMEM_H>>>();
    k_cand  <<<dim3(64, 4), 256, SMEM_H>>>();
    k_exact <<<64, 256>>>(z, emb);
    k_gather<<<512, 256>>>(z, emb, out);
    k_final <<<1, 256>>>(out);
}